// round 16
// baseline (speedup 1.0000x reference)
#include <cuda_runtime.h>
#include <cstdint>

// probs: float32 [50,50,50,50] -> 6,250,000 floats (row-major)
// X:     int32   [8,000,000, 4]
// out:   float32 [8,000,000]
//
// out[i] = probs[ ((X0*50 + X1)*50 + X2)*50 + X3 ]
//
// Final block-size calibration on the optimal configuration:
//  - identical per-thread work to the 43.5us kernel (quarter-warp predicated
//    __ldcg gathers, __ldcs X, __stcs out, UNROLL=4, 24 regs)
//  - THREADS 256 -> 128: doubles CTA count, halves each CTA's front-batched
//    LDG burst into the L1tex queue (multi-CTA spread model: spread grows
//    with oe*MLP_p1 queue contention; finer CTA granularity lets wave
//    work-stealing balance SM completion times).

constexpr int THREADS = 128;
constexpr int UNROLL  = 4;
constexpr int TILE    = THREADS * UNROLL;  // 512 samples per block

__global__ __launch_bounds__(THREADS) void joint_cat_gather_b128(
    const float* __restrict__ probs,
    const int4* __restrict__ X,
    float* __restrict__ out,
    int n)
{
    int base = blockIdx.x * TILE + threadIdx.x;
    int lane_group = (threadIdx.x & 31) >> 3;   // 0..3

    if (base + (UNROLL - 1) * THREADS < n) {
        // ---- fast path: full tile ----
        int4 x[UNROLL];
#pragma unroll
        for (int k = 0; k < UNROLL; k++)
            x[k] = __ldcs(&X[base + k * THREADS]);     // streaming coalesced 16B loads

        int idx[UNROLL];
#pragma unroll
        for (int k = 0; k < UNROLL; k++)
            idx[k] = ((x[k].x * 50 + x[k].y) * 50 + x[k].z) * 50 + x[k].w;

        float r[UNROLL];
        // 16 predicated LDG.cg, each with 8 active lanes.
#pragma unroll
        for (int j = 0; j < 4; j++) {
#pragma unroll
            for (int k = 0; k < UNROLL; k++) {
                if (lane_group == j)
                    r[k] = __ldcg(probs + idx[k]);     // L2-only gather, no L1 fill
            }
        }

#pragma unroll
        for (int k = 0; k < UNROLL; k++)
            __stcs(&out[base + k * THREADS], r[k]);    // streaming coalesced stores
    } else {
        // ---- tail: per-element guard ----
#pragma unroll
        for (int k = 0; k < UNROLL; k++) {
            int i = base + k * THREADS;
            if (i < n) {
                int4 x = __ldcs(&X[i]);
                int idx = ((x.x * 50 + x.y) * 50 + x.z) * 50 + x.w;
                __stcs(&out[i], __ldcg(probs + idx));
            }
        }
    }
}

extern "C" void kernel_launch(void* const* d_in, const int* in_sizes, int n_in,
                              void* d_out, int out_size)
{
    const float* probs = (const float*)d_in[0];
    const int4* X = (const int4*)d_in[1];
    float* out = (float*)d_out;

    int n = out_size;  // 8,000,000 samples
    int blocks = (n + TILE - 1) / TILE;
    joint_cat_gather_b128<<<blocks, THREADS>>>(probs, X, out, n);
}